// round 11
// baseline (speedup 1.0000x reference)
#include <cuda_runtime.h>

#define NBATCH   4
#define NPTS     8192
#define THREADS  128
#define QPT      8                       // rec queries per thread
#define QBLK     (THREADS * QPT)         // 1024 rec rows per block
#define CHUNKS   (NPTS / QBLK)           // 8 row chunks
#define SLICES   32                      // data (col) split
#define DBS      (NPTS / SLICES)         // 256 data points per block
#define BLOCKS_PER_B (CHUNKS * SLICES)   // 256 blocks per batch

// One pass over unique pairs feeds BOTH reductions:
// g_rows[b][slice][n] : per-rec-row min over this block's 256 data cols
// g_cols[b][chunk][m] : per-data-col min over this block's 1024 rec rows
__device__ float        g_rows[NBATCH][SLICES][NPTS];
__device__ float        g_cols[NBATCH][CHUNKS][NPTS];
__device__ float        g_pb[NBATCH];
__device__ unsigned int g_cnt[NBATCH];   // zero-init; reset by final finisher
__device__ unsigned int g_cnt2;          // zero-init; reset by final finisher

typedef unsigned long long ull;

__device__ __forceinline__ ull ffma2(ull a, ull b, ull c) {
    ull d;
    asm("fma.rn.f32x2 %0, %1, %2, %3;" : "=l"(d) : "l"(a), "l"(b), "l"(c));
    return d;
}
__device__ __forceinline__ ull fadd2(ull a, ull b) {
    ull d;
    asm("add.rn.f32x2 %0, %1, %2;" : "=l"(d) : "l"(a), "l"(b));
    return d;
}
__device__ __forceinline__ ull pack2(float lo, float hi) {
    ull d;
    asm("mov.b64 %0, {%1, %2};" : "=l"(d) : "f"(lo), "f"(hi));
    return d;
}
__device__ __forceinline__ float2 unpack2(ull v) {
    float2 r;
    asm("mov.b64 {%0, %1}, %2;" : "=f"(r.x), "=f"(r.y) : "l"(v));
    return r;
}
// packed min = 2 scalar FMNMX on the register pair (unpack/pack are free)
__device__ __forceinline__ ull pmin(ull a, ull b) {
    float2 x = unpack2(a), y = unpack2(b);
    return pack2(fminf(x.x, y.x), fminf(x.y, y.y));
}

__global__ __launch_bounds__(THREADS, 4)
void chamfer_main(const float* __restrict__ rec,
                  const float* __restrict__ data,
                  float* __restrict__ out) {
    __shared__ float s0[DBS];
    __shared__ float s1[DBS];
    __shared__ float s2[DBS];
    __shared__ float sn[DBS];
    __shared__ float colw[4][DBS];   // per-warp col mins
    __shared__ float red[THREADS];
    __shared__ float s_rowsum;
    __shared__ int   s_flag;

    const int tid   = threadIdx.x;
    const int lane  = tid & 31;
    const int wid   = tid >> 5;
    const int slice = blockIdx.x & (SLICES - 1);
    const int chunk = blockIdx.x >> 5;
    const int b     = blockIdx.y;

    // ---- Load data slice into SMEM (SoA + norms) ----
    const float* dbb = data + ((size_t)b * NPTS + slice * DBS) * 3;
    for (int i = tid; i < DBS; i += THREADS) {
        float x = dbb[3 * i + 0];
        float y = dbb[3 * i + 1];
        float z = dbb[3 * i + 2];
        s0[i] = x;
        s1[i] = y;
        s2[i] = z;
        sn[i] = fmaf(x, x, fmaf(y, y, z * z));
    }

    // ---- Per-thread rec query points ----
    ull Q2[QPT], A0[QPT], A1[QPT], A2[QPT];
    #pragma unroll
    for (int q = 0; q < QPT; ++q) {
        int qi = chunk * QBLK + q * THREADS + tid;
        const float* qp = rec + ((size_t)b * NPTS + qi) * 3;
        float qx = qp[0], qy = qp[1], qz = qp[2];
        float q2 = fmaf(qx, qx, fmaf(qy, qy, qz * qz));
        Q2[q] = pack2(q2, q2);
        A0[q] = pack2(-2.0f * qx, -2.0f * qx);
        A1[q] = pack2(-2.0f * qy, -2.0f * qy);
        A2[q] = pack2(-2.0f * qz, -2.0f * qz);
    }

    __syncthreads();

    // ---- Main loop: full distance d = q2 - 2 x.y + sn, 4 cols / step.
    //      Each unique pair feeds BOTH row-min (regs) and col-min (warp). ----
    ull mA[QPT], mB[QPT];
    const ull big = pack2(1e30f, 1e30f);
    #pragma unroll
    for (int q = 0; q < QPT; ++q) { mA[q] = big; mB[q] = big; }

    #pragma unroll 1
    for (int j = 0; j < DBS; j += 4) {
        ulonglong2 p0 = *reinterpret_cast<const ulonglong2*>(s0 + j);
        ulonglong2 p1 = *reinterpret_cast<const ulonglong2*>(s1 + j);
        ulonglong2 p2 = *reinterpret_cast<const ulonglong2*>(s2 + j);
        ulonglong2 pn = *reinterpret_cast<const ulonglong2*>(sn + j);

        ull colA = big, colB = big;

        #pragma unroll
        for (int q = 0; q < QPT; ++q) {
            ull accA = ffma2(A2[q], p2.x, Q2[q]);
            accA     = ffma2(A1[q], p1.x, accA);
            accA     = ffma2(A0[q], p0.x, accA);
            ull fA   = fadd2(accA, pn.x);          // full distances, cols j,j+1
            mA[q]    = pmin(mA[q], fA);
            colA     = pmin(colA, fA);

            ull accB = ffma2(A2[q], p2.y, Q2[q]);
            accB     = ffma2(A1[q], p1.y, accB);
            accB     = ffma2(A0[q], p0.y, accB);
            ull fB   = fadd2(accB, pn.y);          // full distances, cols j+2,j+3
            mB[q]    = pmin(mB[q], fB);
            colB     = pmin(colB, fB);
        }

        // warp-reduce col mins (cols unique to this body -> plain store)
        #pragma unroll
        for (int m = 16; m > 0; m >>= 1) {
            colA = pmin(colA, __shfl_xor_sync(0xffffffffu, colA, m));
            colB = pmin(colB, __shfl_xor_sync(0xffffffffu, colB, m));
        }
        if (lane == 0) {
            *reinterpret_cast<ull*>(&colw[wid][j])     = colA;
            *reinterpret_cast<ull*>(&colw[wid][j + 2]) = colB;
        }
    }

    __syncthreads();

    // ---- Combine 4 warps' col mins -> global (coalesced) ----
    for (int c = tid; c < DBS; c += THREADS) {
        float v = fminf(fminf(colw[0][c], colw[1][c]),
                        fminf(colw[2][c], colw[3][c]));
        g_cols[b][chunk][slice * DBS + c] = v;
    }

    // ---- Row mins -> global (coalesced) ----
    const int base = chunk * QBLK + tid;
    #pragma unroll
    for (int q = 0; q < QPT; ++q) {
        float2 f = unpack2(pmin(mA[q], mB[q]));
        g_rows[b][slice][base + q * THREADS] = fminf(f.x, f.y);
    }

    // ---- Fused reduce: last block of each batch reduces that batch ----
    if (tid == 0) {
        __threadfence();
        unsigned int t = atomicAdd(&g_cnt[b], 1u);
        s_flag = (t == BLOCKS_PER_B - 1) ? 1 : 0;
    }
    __syncthreads();

    if (s_flag) {
        __threadfence();   // acquire: all g_rows/g_cols writes visible
        // rec side: min over 32 slices, clamp, sum
        float srow = 0.0f;
        for (int r = tid * 4; r < NPTS; r += THREADS * 4) {
            float4 m = *reinterpret_cast<const float4*>(&g_rows[b][0][r]);
            #pragma unroll
            for (int s = 1; s < SLICES; ++s) {
                float4 v = *reinterpret_cast<const float4*>(&g_rows[b][s][r]);
                m.x = fminf(m.x, v.x);
                m.y = fminf(m.y, v.y);
                m.z = fminf(m.z, v.z);
                m.w = fminf(m.w, v.w);
            }
            srow += (fmaxf(m.x, 0.0f) + fmaxf(m.y, 0.0f)) +
                    (fmaxf(m.z, 0.0f) + fmaxf(m.w, 0.0f));
        }
        red[tid] = srow;
        __syncthreads();
        #pragma unroll
        for (int st = THREADS / 2; st > 0; st >>= 1) {
            if (tid < st) red[tid] += red[tid + st];
            __syncthreads();
        }
        if (tid == 0) s_rowsum = red[0];
        __syncthreads();

        // data side: min over 8 chunks, clamp, sum
        float scol = 0.0f;
        for (int c = tid * 4; c < NPTS; c += THREADS * 4) {
            float4 m = *reinterpret_cast<const float4*>(&g_cols[b][0][c]);
            #pragma unroll
            for (int ch = 1; ch < CHUNKS; ++ch) {
                float4 v = *reinterpret_cast<const float4*>(&g_cols[b][ch][c]);
                m.x = fminf(m.x, v.x);
                m.y = fminf(m.y, v.y);
                m.z = fminf(m.z, v.z);
                m.w = fminf(m.w, v.w);
            }
            scol += (fmaxf(m.x, 0.0f) + fmaxf(m.y, 0.0f)) +
                    (fmaxf(m.z, 0.0f) + fmaxf(m.w, 0.0f));
        }
        red[tid] = scol;
        __syncthreads();
        #pragma unroll
        for (int st = THREADS / 2; st > 0; st >>= 1) {
            if (tid < st) red[tid] += red[tid + st];
            __syncthreads();
        }

        if (tid == 0) {
            float mean_rec = s_rowsum * (1.0f / NPTS);
            float mean_dat = red[0]   * (1.0f / NPTS);
            g_pb[b] = fmaxf(mean_rec, mean_dat);
            __threadfence();
            unsigned int t2 = atomicAdd(&g_cnt2, 1u);
            if (t2 == NBATCH - 1) {
                __threadfence();
                float total = 0.0f;
                #pragma unroll
                for (int bb = 0; bb < NBATCH; ++bb) total += g_pb[bb];
                out[0] = total * (1.0f / NBATCH);
                #pragma unroll
                for (int bb = 0; bb < NBATCH; ++bb) g_cnt[bb] = 0u;
                g_cnt2 = 0u;
            }
        }
    }
}

extern "C" void kernel_launch(void* const* d_in, const int* in_sizes, int n_in,
                              void* d_out, int out_size) {
    const float* rec  = (const float*)d_in[0];   // (B, N, 3) fp32
    const float* data = (const float*)d_in[1];   // (B, M, 3) fp32
    float* out = (float*)d_out;

    dim3 grid(CHUNKS * SLICES, NBATCH);          // 256 x 4 = 1024 blocks
    chamfer_main<<<grid, THREADS>>>(rec, data, out);
}